// round 3
// baseline (speedup 1.0000x reference)
#include <cuda_runtime.h>
#include <cuda_bf16.h>
#include <cstdint>
#include <cstddef>

#define B_   2
#define T_   2048
#define C_   1024
#define NH_  16
#define HD_  64
#define C3_  3072
#define ROWS_ (B_ * T_)      // 4096

// ---------------------------------------------------------------------------
// Scratch (allocation-free rule: __device__ globals)
// ---------------------------------------------------------------------------
__device__ float g_qkv[(size_t)ROWS_ * C3_];   // 48 MB
__device__ float g_y[(size_t)ROWS_ * C_];      // 16 MB

// ---------------------------------------------------------------------------
// Helpers
// ---------------------------------------------------------------------------
__device__ __forceinline__ float f2tf32(float x) {
    uint32_t u;
    asm("cvt.rna.tf32.f32 %0, %1;" : "=r"(u) : "f"(x));
    return __uint_as_float(u);
}

__device__ __forceinline__ void mma_tf32(float d[4], const uint32_t a[4], const uint32_t b[2]) {
    asm volatile(
        "mma.sync.aligned.m16n8k8.row.col.f32.tf32.tf32.f32 "
        "{%0,%1,%2,%3}, {%4,%5,%6,%7}, {%8,%9}, {%0,%1,%2,%3};\n"
        : "+f"(d[0]), "+f"(d[1]), "+f"(d[2]), "+f"(d[3])
        : "r"(a[0]), "r"(a[1]), "r"(a[2]), "r"(a[3]), "r"(b[0]), "r"(b[1]));
}

// ---------------------------------------------------------------------------
// TF32 GEMM: C[M,N] = A[M,K] * B[K,N], all row-major fp32.
// Block tile 128x128x32, 256 threads, warp grid 4(m) x 2(n), warp tile 32x64.
// ---------------------------------------------------------------------------
#define GBM 128
#define GBN 128
#define GBK 32
#define AS_STRIDE 36     // (4m + k) % 32 distinct -> conflict-free a-frag reads
#define BS_STRIDE 136    // (8k + n) % 32 distinct -> conflict-free b-frag reads

__global__ __launch_bounds__(256, 2)
void gemm_tf32_kernel(const float* __restrict__ A, const float* __restrict__ Bm,
                      float* __restrict__ Cm, int M, int N, int K)
{
    __shared__ float As[GBM * AS_STRIDE];
    __shared__ float Bs[GBK * BS_STRIDE];

    const int tid  = threadIdx.x;
    const int lane = tid & 31;
    const int warp = tid >> 5;
    const int wm   = warp & 3;        // 0..3
    const int wn   = warp >> 2;       // 0..1
    const int g    = lane >> 2;       // group id (row within 8)
    const int tg   = lane & 3;        // thread in group

    const int bm = blockIdx.y * GBM;
    const int bn = blockIdx.x * GBN;

    float acc[2][8][4];
    #pragma unroll
    for (int i = 0; i < 2; i++)
        #pragma unroll
        for (int j = 0; j < 8; j++)
            #pragma unroll
            for (int k = 0; k < 4; k++) acc[i][j][k] = 0.f;

    const int a_row = tid >> 3;          // 0..31
    const int a_col = (tid & 7) * 4;     // 0..28
    const int b_row = tid >> 5;          // 0..7
    const int b_col = (tid & 31) * 4;    // 0..124

    for (int kb = 0; kb < K; kb += GBK) {
        // A tile 128x32 (converted to tf32 at STS time)
        #pragma unroll
        for (int p = 0; p < 4; p++) {
            const int r = a_row + p * 32;
            const float4 v = *(const float4*)&A[(size_t)(bm + r) * K + kb + a_col];
            float* dst = &As[r * AS_STRIDE + a_col];
            dst[0] = f2tf32(v.x); dst[1] = f2tf32(v.y);
            dst[2] = f2tf32(v.z); dst[3] = f2tf32(v.w);
        }
        // B tile 32x128
        #pragma unroll
        for (int p = 0; p < 4; p++) {
            const int r = b_row + p * 8;
            const float4 v = *(const float4*)&Bm[(size_t)(kb + r) * N + bn + b_col];
            float* dst = &Bs[r * BS_STRIDE + b_col];
            dst[0] = f2tf32(v.x); dst[1] = f2tf32(v.y);
            dst[2] = f2tf32(v.z); dst[3] = f2tf32(v.w);
        }
        __syncthreads();

        #pragma unroll
        for (int kk = 0; kk < 4; kk++) {
            uint32_t af[2][4], bf[8][2];
            #pragma unroll
            for (int mt = 0; mt < 2; mt++) {
                const int rb = wm * 32 + mt * 16 + g;
                const int c  = kk * 8 + tg;
                af[mt][0] = __float_as_uint(As[rb * AS_STRIDE + c]);
                af[mt][1] = __float_as_uint(As[(rb + 8) * AS_STRIDE + c]);
                af[mt][2] = __float_as_uint(As[rb * AS_STRIDE + c + 4]);
                af[mt][3] = __float_as_uint(As[(rb + 8) * AS_STRIDE + c + 4]);
            }
            #pragma unroll
            for (int nt = 0; nt < 8; nt++) {
                const int cc = wn * 64 + nt * 8 + g;
                bf[nt][0] = __float_as_uint(Bs[(kk * 8 + tg) * BS_STRIDE + cc]);
                bf[nt][1] = __float_as_uint(Bs[(kk * 8 + tg + 4) * BS_STRIDE + cc]);
            }
            #pragma unroll
            for (int mt = 0; mt < 2; mt++)
                #pragma unroll
                for (int nt = 0; nt < 8; nt++)
                    mma_tf32(acc[mt][nt], af[mt], bf[nt]);
        }
        __syncthreads();
    }

    // Epilogue: c0,c1 -> (r, 2tg), (r, 2tg+1); c2,c3 -> row+8
    #pragma unroll
    for (int mt = 0; mt < 2; mt++) {
        const int r0 = bm + wm * 32 + mt * 16 + g;
        #pragma unroll
        for (int nt = 0; nt < 8; nt++) {
            const int cc = bn + wn * 64 + nt * 8 + 2 * tg;
            *(float2*)&Cm[(size_t)r0 * N + cc]       = make_float2(acc[mt][nt][0], acc[mt][nt][1]);
            *(float2*)&Cm[(size_t)(r0 + 8) * N + cc] = make_float2(acc[mt][nt][2], acc[mt][nt][3]);
        }
    }
}

// ---------------------------------------------------------------------------
// Flash attention, TF32 MMA. One block per (q-tile of 64, b*h).
// 4 warps x 16 q-rows; KV tile 64; HD=64.
// smem: Ks[64][68] (kv-major), Vts[64][68] (hd-major), Ps[4 warps][16][68]
// ---------------------------------------------------------------------------
#define ATT_SMEM_FLOATS (2 * 64 * 68 + 4 * 16 * 68)   // 13056 floats = 52224 B

__global__ __launch_bounds__(128)
void attn_kernel(const float* __restrict__ qkv, float* __restrict__ y)
{
    extern __shared__ float smem[];
    float* Ks  = smem;               // [kv 64][hd 68]
    float* Vts = smem + 64 * 68;     // [hd 64][kv 68]
    float* Ps  = smem + 2 * 64 * 68; // [warp 4][q 16][kv 68]

    const int tid  = threadIdx.x;
    const int lane = tid & 31;
    const int warp = tid >> 5;
    const int g    = lane >> 2;
    const int tg   = lane & 3;

    const int qt = blockIdx.x;            // q tile (0..31)
    const int bh = blockIdx.y;            // 0..31
    const int b  = bh / NH_;
    const int h  = bh % NH_;

    const float* base = qkv + (size_t)b * T_ * C3_;
    const int qcol = h * HD_;
    const int kcol = C_ + h * HD_;
    const int vcol = 2 * C_ + h * HD_;

    // Q a-fragments in registers, pre-scaled by 1/sqrt(64), tf32-rounded.
    uint32_t qf[8][4];
    {
        const int r0 = qt * 64 + warp * 16 + g;
        const float sc = 0.125f;
        #pragma unroll
        for (int ks = 0; ks < 8; ks++) {
            const int c = qcol + ks * 8 + tg;
            qf[ks][0] = __float_as_uint(f2tf32(base[(size_t)r0 * C3_ + c] * sc));
            qf[ks][1] = __float_as_uint(f2tf32(base[(size_t)(r0 + 8) * C3_ + c] * sc));
            qf[ks][2] = __float_as_uint(f2tf32(base[(size_t)r0 * C3_ + c + 4] * sc));
            qf[ks][3] = __float_as_uint(f2tf32(base[(size_t)(r0 + 8) * C3_ + c + 4] * sc));
        }
    }

    float o[8][4];
    #pragma unroll
    for (int i = 0; i < 8; i++)
        #pragma unroll
        for (int jj = 0; jj < 4; jj++) o[i][jj] = 0.f;
    float m0 = -INFINITY, m1 = -INFINITY, l0 = 0.f, l1 = 0.f;

    const int ld_r = tid >> 4;          // 0..7
    const int ld_c = (tid & 15) * 4;    // 0..60

    for (int j = 0; j <= qt; j++) {
        __syncthreads();   // previous tile's Ks/Vts/Ps reads complete
        #pragma unroll
        for (int p = 0; p < 8; p++) {
            const int r = ld_r + p * 8;
            const size_t grow = (size_t)(j * 64 + r) * C3_;
            const float4 k4 = *(const float4*)&base[grow + kcol + ld_c];
            float* kd = &Ks[r * 68 + ld_c];
            kd[0] = f2tf32(k4.x); kd[1] = f2tf32(k4.y);
            kd[2] = f2tf32(k4.z); kd[3] = f2tf32(k4.w);
            const float4 v4 = *(const float4*)&base[grow + vcol + ld_c];
            Vts[(ld_c + 0) * 68 + r] = f2tf32(v4.x);
            Vts[(ld_c + 1) * 68 + r] = f2tf32(v4.y);
            Vts[(ld_c + 2) * 68 + r] = f2tf32(v4.z);
            Vts[(ld_c + 3) * 68 + r] = f2tf32(v4.w);
        }
        __syncthreads();

        // S = (Q*scale) @ K^T     (16 q-rows per warp x 64 kv)
        float s[8][4];
        #pragma unroll
        for (int nt = 0; nt < 8; nt++)
            #pragma unroll
            for (int k4 = 0; k4 < 4; k4++) s[nt][k4] = 0.f;

        #pragma unroll
        for (int ks = 0; ks < 8; ks++) {
            #pragma unroll
            for (int nt = 0; nt < 8; nt++) {
                uint32_t bf[2];
                bf[0] = __float_as_uint(Ks[(nt * 8 + g) * 68 + ks * 8 + tg]);
                bf[1] = __float_as_uint(Ks[(nt * 8 + g) * 68 + ks * 8 + tg + 4]);
                mma_tf32(s[nt], qf[ks], bf);
            }
        }

        // Causal mask (diagonal tile only; earlier tiles fully unmasked)
        if (j == qt) {
            const int q0 = warp * 16 + g, q1 = q0 + 8;
            #pragma unroll
            for (int nt = 0; nt < 8; nt++) {
                const int c0 = nt * 8 + 2 * tg;
                if (c0     > q0) s[nt][0] = -1e30f;
                if (c0 + 1 > q0) s[nt][1] = -1e30f;
                if (c0     > q1) s[nt][2] = -1e30f;
                if (c0 + 1 > q1) s[nt][3] = -1e30f;
            }
        }

        // Online softmax (rows split per lane: row g -> s[.][0,1], row g+8 -> s[.][2,3])
        float mt0 = -INFINITY, mt1 = -INFINITY;
        #pragma unroll
        for (int nt = 0; nt < 8; nt++) {
            mt0 = fmaxf(mt0, fmaxf(s[nt][0], s[nt][1]));
            mt1 = fmaxf(mt1, fmaxf(s[nt][2], s[nt][3]));
        }
        mt0 = fmaxf(mt0, __shfl_xor_sync(0xffffffffu, mt0, 1));
        mt0 = fmaxf(mt0, __shfl_xor_sync(0xffffffffu, mt0, 2));
        mt1 = fmaxf(mt1, __shfl_xor_sync(0xffffffffu, mt1, 1));
        mt1 = fmaxf(mt1, __shfl_xor_sync(0xffffffffu, mt1, 2));

        const float mn0 = fmaxf(m0, mt0), mn1 = fmaxf(m1, mt1);
        const float f0 = __expf(m0 - mn0), f1 = __expf(m1 - mn1);

        float ls0 = 0.f, ls1 = 0.f;
        float* prow0 = &Ps[warp * 16 * 68 + g * 68];
        float* prow1 = prow0 + 8 * 68;
        #pragma unroll
        for (int nt = 0; nt < 8; nt++) {
            const float p0 = __expf(s[nt][0] - mn0);
            const float p1 = __expf(s[nt][1] - mn0);
            const float p2 = __expf(s[nt][2] - mn1);
            const float p3 = __expf(s[nt][3] - mn1);
            ls0 += p0 + p1; ls1 += p2 + p3;
            const int c = nt * 8 + 2 * tg;
            *(float2*)&prow0[c] = make_float2(f2tf32(p0), f2tf32(p1));
            *(float2*)&prow1[c] = make_float2(f2tf32(p2), f2tf32(p3));
        }
        ls0 += __shfl_xor_sync(0xffffffffu, ls0, 1);
        ls0 += __shfl_xor_sync(0xffffffffu, ls0, 2);
        ls1 += __shfl_xor_sync(0xffffffffu, ls1, 1);
        ls1 += __shfl_xor_sync(0xffffffffu, ls1, 2);

        l0 = l0 * f0 + ls0;
        l1 = l1 * f1 + ls1;
        m0 = mn0; m1 = mn1;

        #pragma unroll
        for (int nt = 0; nt < 8; nt++) {
            o[nt][0] *= f0; o[nt][1] *= f0;
            o[nt][2] *= f1; o[nt][3] *= f1;
        }
        __syncwarp();   // cross-lane P writes -> a-frag reads (same warp)

        // O += P @ V
        float* pbase = &Ps[warp * 16 * 68];
        #pragma unroll
        for (int ks = 0; ks < 8; ks++) {
            uint32_t af[4];
            af[0] = __float_as_uint(pbase[g * 68 + ks * 8 + tg]);
            af[1] = __float_as_uint(pbase[(g + 8) * 68 + ks * 8 + tg]);
            af[2] = __float_as_uint(pbase[g * 68 + ks * 8 + tg + 4]);
            af[3] = __float_as_uint(pbase[(g + 8) * 68 + ks * 8 + tg + 4]);
            #pragma unroll
            for (int nt = 0; nt < 8; nt++) {
                uint32_t bf[2];
                bf[0] = __float_as_uint(Vts[(nt * 8 + g) * 68 + ks * 8 + tg]);
                bf[1] = __float_as_uint(Vts[(nt * 8 + g) * 68 + ks * 8 + tg + 4]);
                mma_tf32(o[nt], af, bf);
            }
        }
    }

    // Normalize and write y
    const float i0 = 1.f / l0, i1 = 1.f / l1;
    const int yr0 = qt * 64 + warp * 16 + g;
    #pragma unroll
    for (int nt = 0; nt < 8; nt++) {
        const int c = h * HD_ + nt * 8 + 2 * tg;
        *(float2*)&y[(size_t)(b * T_ + yr0) * C_ + c]     = make_float2(o[nt][0] * i0, o[nt][1] * i0);
        *(float2*)&y[(size_t)(b * T_ + yr0 + 8) * C_ + c] = make_float2(o[nt][2] * i1, o[nt][3] * i1);
    }
}

// ---------------------------------------------------------------------------
// Launch: qkv GEMM -> attention -> proj GEMM (stream-ordered, graph-capturable)
// ---------------------------------------------------------------------------
extern "C" void kernel_launch(void* const* d_in, const int* in_sizes, int n_in,
                              void* d_out, int out_size)
{
    (void)in_sizes; (void)n_in; (void)out_size;
    const float* x      = (const float*)d_in[0];
    const float* w_attn = (const float*)d_in[1];
    const float* w_proj = (const float*)d_in[2];
    float* out = (float*)d_out;

    float* qkv = nullptr;
    float* y   = nullptr;
    cudaGetSymbolAddress((void**)&qkv, g_qkv);
    cudaGetSymbolAddress((void**)&y, g_y);

    const size_t att_smem = (size_t)ATT_SMEM_FLOATS * sizeof(float);  // 52224 B
    cudaFuncSetAttribute(attn_kernel, cudaFuncAttributeMaxDynamicSharedMemorySize, (int)att_smem);

    gemm_tf32_kernel<<<dim3(C3_ / GBN, ROWS_ / GBM), 256>>>(x, w_attn, qkv, ROWS_, C3_, C_);
    attn_kernel<<<dim3(T_ / 64, B_ * NH_), 128, att_smem>>>(qkv, y);
    gemm_tf32_kernel<<<dim3(C_ / GBN, ROWS_ / GBM), 256>>>(y, w_proj, out, ROWS_, C_, C_);
}

// round 4
// speedup vs baseline: 1.0400x; 1.0400x over previous
#include <cuda_runtime.h>
#include <cstdint>
#include <cstddef>

#define B_   2
#define T_   2048
#define C_   1024
#define NH_  16
#define HD_  64
#define C3_  3072
#define ROWS_ 4096

// ---------------------------------------------------------------------------
// Scratch (__device__ globals; allocation-free rule)
// ---------------------------------------------------------------------------
__device__ float g_qkv[(size_t)ROWS_ * C3_];   // 48 MB (tf32-rounded by gemm epilogue)
__device__ float g_y[(size_t)ROWS_ * C_];      // 16 MB (tf32-rounded by attn epilogue)
__device__ float g_xr[(size_t)ROWS_ * C_];     // 16 MB pre-rounded x
__device__ float g_war[(size_t)C_ * C3_];      // 12 MB pre-rounded w_attn
__device__ float g_wpr[(size_t)C_ * C_];       //  4 MB pre-rounded w_proj

// ---------------------------------------------------------------------------
// Helpers
// ---------------------------------------------------------------------------
__device__ __forceinline__ float f2tf32(float x) {
    uint32_t u;
    asm("cvt.rna.tf32.f32 %0, %1;" : "=r"(u) : "f"(x));
    return __uint_as_float(u);
}

__device__ __forceinline__ void mma_tf32(float d[4], const uint32_t a[4], const uint32_t b[2]) {
    asm volatile(
        "mma.sync.aligned.m16n8k8.row.col.f32.tf32.tf32.f32 "
        "{%0,%1,%2,%3}, {%4,%5,%6,%7}, {%8,%9}, {%0,%1,%2,%3};\n"
        : "+f"(d[0]), "+f"(d[1]), "+f"(d[2]), "+f"(d[3])
        : "r"(a[0]), "r"(a[1]), "r"(a[2]), "r"(a[3]), "r"(b[0]), "r"(b[1]));
}

__device__ __forceinline__ void cp_async16(void* smem_dst, const void* gsrc) {
    uint32_t s = (uint32_t)__cvta_generic_to_shared(smem_dst);
    asm volatile("cp.async.ca.shared.global [%0], [%1], 16;\n" :: "r"(s), "l"(gsrc));
}
#define CP_COMMIT asm volatile("cp.async.commit_group;\n" ::: "memory")
#define CP_WAIT_1 asm volatile("cp.async.wait_group 1;\n" ::: "memory")
#define CP_WAIT_0 asm volatile("cp.async.wait_group 0;\n" ::: "memory")

// ---------------------------------------------------------------------------
// Elementwise tf32 pre-round (inputs must be tf32 so cp.async needs no cvt)
// ---------------------------------------------------------------------------
__global__ void round_tf32_kernel(const float4* __restrict__ in, float4* __restrict__ out, int n4)
{
    int i = blockIdx.x * 256 + threadIdx.x;
    if (i < n4) {
        float4 v = in[i];
        v.x = f2tf32(v.x); v.y = f2tf32(v.y);
        v.z = f2tf32(v.z); v.w = f2tf32(v.w);
        out[i] = v;
    }
}

// ---------------------------------------------------------------------------
// TF32 GEMM with cp.async double-buffered pipeline.
// C[M,N] = A[M,K]*B[K,N], row-major, inputs already tf32-rounded.
// Block 128x128x32, 256 threads, warp grid 4(m)x2(n), warp tile 32x64.
// ---------------------------------------------------------------------------
#define GBM 128
#define GBN 128
#define GBK 32
#define ASTR 36     // 4 mod 32 -> conflict-free a-frag reads
#define BSTR 136    // 8 mod 32 -> conflict-free b-frag reads
#define A_BUF (GBM * ASTR)                    // 4608 floats
#define B_BUF (GBK * BSTR)                    // 4352 floats
#define GEMM_SMEM ((2 * A_BUF + 2 * B_BUF) * 4)   // 71680 B

template<bool ROUND_OUT>
__global__ __launch_bounds__(256, 2)
void gemm_tf32_cp(const float* __restrict__ A, const float* __restrict__ Bm,
                  float* __restrict__ Cm, int M, int N, int K)
{
    extern __shared__ float sm[];
    const int tid  = threadIdx.x;
    const int lane = tid & 31;
    const int warp = tid >> 5;
    const int wm   = warp & 3;
    const int wn   = warp >> 2;
    const int g    = lane >> 2;
    const int tg   = lane & 3;
    const int bm   = blockIdx.y * GBM;
    const int bn   = blockIdx.x * GBN;

    float acc[2][8][4];
    #pragma unroll
    for (int i = 0; i < 2; i++)
        #pragma unroll
        for (int j = 0; j < 8; j++)
            #pragma unroll
            for (int k = 0; k < 4; k++) acc[i][j][k] = 0.f;

    auto load_stage = [&](int kb, int buf) {
        float* As = sm + buf * A_BUF;
        float* Bs = sm + 2 * A_BUF + buf * B_BUF;
        #pragma unroll
        for (int p = 0; p < 4; p++) {
            int idx = tid + p * 256;
            int r = idx >> 3, c = (idx & 7) * 4;
            cp_async16(&As[r * ASTR + c], &A[(size_t)(bm + r) * K + kb * GBK + c]);
        }
        #pragma unroll
        for (int p = 0; p < 4; p++) {
            int idx = tid + p * 256;
            int r = idx >> 5, c = (idx & 31) * 4;
            cp_async16(&Bs[r * BSTR + c], &Bm[(size_t)(kb * GBK + r) * N + bn + c]);
        }
    };

    const int nk = K / GBK;
    load_stage(0, 0); CP_COMMIT;

    for (int kb = 0; kb < nk; kb++) {
        const int cur = kb & 1;
        if (kb + 1 < nk) { load_stage(kb + 1, cur ^ 1); CP_COMMIT; CP_WAIT_1; }
        else             { CP_WAIT_0; }
        __syncthreads();

        const float* As = sm + cur * A_BUF;
        const float* Bs = sm + 2 * A_BUF + cur * B_BUF;

        #pragma unroll
        for (int kk = 0; kk < 4; kk++) {
            uint32_t af[2][4], bf[8][2];
            #pragma unroll
            for (int mt = 0; mt < 2; mt++) {
                const int rb = wm * 32 + mt * 16 + g;
                const int c  = kk * 8 + tg;
                af[mt][0] = __float_as_uint(As[rb * ASTR + c]);
                af[mt][1] = __float_as_uint(As[(rb + 8) * ASTR + c]);
                af[mt][2] = __float_as_uint(As[rb * ASTR + c + 4]);
                af[mt][3] = __float_as_uint(As[(rb + 8) * ASTR + c + 4]);
            }
            #pragma unroll
            for (int nt = 0; nt < 8; nt++) {
                const int cc = wn * 64 + nt * 8 + g;
                bf[nt][0] = __float_as_uint(Bs[(kk * 8 + tg) * BSTR + cc]);
                bf[nt][1] = __float_as_uint(Bs[(kk * 8 + tg + 4) * BSTR + cc]);
            }
            #pragma unroll
            for (int mt = 0; mt < 2; mt++)
                #pragma unroll
                for (int nt = 0; nt < 8; nt++)
                    mma_tf32(acc[mt][nt], af[mt], bf[nt]);
        }
        __syncthreads();
    }

    #pragma unroll
    for (int mt = 0; mt < 2; mt++) {
        const int r0 = bm + wm * 32 + mt * 16 + g;
        #pragma unroll
        for (int nt = 0; nt < 8; nt++) {
            const int cc = bn + wn * 64 + nt * 8 + 2 * tg;
            float2 v0, v1;
            if (ROUND_OUT) {
                v0 = make_float2(f2tf32(acc[mt][nt][0]), f2tf32(acc[mt][nt][1]));
                v1 = make_float2(f2tf32(acc[mt][nt][2]), f2tf32(acc[mt][nt][3]));
            } else {
                v0 = make_float2(acc[mt][nt][0], acc[mt][nt][1]);
                v1 = make_float2(acc[mt][nt][2], acc[mt][nt][3]);
            }
            *(float2*)&Cm[(size_t)r0 * N + cc]       = v0;
            *(float2*)&Cm[(size_t)(r0 + 8) * N + cc] = v1;
        }
    }
}

// ---------------------------------------------------------------------------
// Flash attention, TF32 MMA, cp.async double-buffered KV.
// One block per (q-tile of 128, b*h). 8 warps x 16 q-rows; KV tile 64.
// smem: Ks[2][64][68], Vs[2][64][68] (untransposed), Ps[8][16][68]
// ---------------------------------------------------------------------------
#define KV_BUF (64 * 68)                       // 4352 floats
#define PS_OFF (4 * KV_BUF)                    // 17408
#define ATT_SMEM ((4 * KV_BUF + 8 * 16 * 68) * 4)   // 104448 B

__global__ __launch_bounds__(256, 2)
void attn_kernel(const float* __restrict__ qkv, float* __restrict__ y)
{
    extern __shared__ float sm[];
    const int tid  = threadIdx.x;
    const int lane = tid & 31;
    const int warp = tid >> 5;
    const int g    = lane >> 2;
    const int tg   = lane & 3;

    const int qt = gridDim.x - 1 - blockIdx.x;   // heavy tiles launch first
    const int bh = blockIdx.y;
    const int b  = bh >> 4;
    const int h  = bh & 15;

    const float* base = qkv + (size_t)b * T_ * C3_;
    const int qcol = h * HD_;
    const int kcol = C_ + h * HD_;
    const int vcol = 2 * C_ + h * HD_;

    auto load_kv = [&](int j, int buf) {
        float* Ksb = sm + buf * KV_BUF;
        float* Vsb = sm + 2 * KV_BUF + buf * KV_BUF;
        #pragma unroll
        for (int p = 0; p < 4; p++) {
            int idx = tid + p * 256;
            int r = idx >> 4, c = (idx & 15) * 4;
            size_t grow = (size_t)(j * 64 + r) * C3_;
            cp_async16(&Ksb[r * 68 + c], &base[grow + kcol + c]);
            cp_async16(&Vsb[r * 68 + c], &base[grow + vcol + c]);
        }
    };

    const int jend = 2 * qt + 1;
    load_kv(0, 0); CP_COMMIT;

    // Q a-fragments (qkv pre-rounded tf32; *0.125 is exact) — overlaps cp.async
    uint32_t qf[8][4];
    {
        const int r0 = qt * 128 + warp * 16 + g;
        #pragma unroll
        for (int ks = 0; ks < 8; ks++) {
            const int c = qcol + ks * 8 + tg;
            qf[ks][0] = __float_as_uint(base[(size_t)r0 * C3_ + c] * 0.125f);
            qf[ks][1] = __float_as_uint(base[(size_t)(r0 + 8) * C3_ + c] * 0.125f);
            qf[ks][2] = __float_as_uint(base[(size_t)r0 * C3_ + c + 4] * 0.125f);
            qf[ks][3] = __float_as_uint(base[(size_t)(r0 + 8) * C3_ + c + 4] * 0.125f);
        }
    }

    float o[8][4];
    #pragma unroll
    for (int i = 0; i < 8; i++)
        #pragma unroll
        for (int jj = 0; jj < 4; jj++) o[i][jj] = 0.f;
    float m0 = -INFINITY, m1 = -INFINITY, l0 = 0.f, l1 = 0.f;

    float* Pw = sm + PS_OFF + warp * 16 * 68;

    for (int j = 0; j <= jend; j++) {
        const int cur = j & 1;
        if (j < jend) { load_kv(j + 1, cur ^ 1); CP_COMMIT; CP_WAIT_1; }
        else          { CP_WAIT_0; }
        __syncthreads();

        const float* Ksb = sm + cur * KV_BUF;
        const float* Vsb = sm + 2 * KV_BUF + cur * KV_BUF;

        // S = (Q*scale) @ K^T
        float s[8][4];
        #pragma unroll
        for (int nt = 0; nt < 8; nt++)
            #pragma unroll
            for (int k4 = 0; k4 < 4; k4++) s[nt][k4] = 0.f;

        #pragma unroll
        for (int ks = 0; ks < 8; ks++) {
            #pragma unroll
            for (int nt = 0; nt < 8; nt++) {
                uint32_t bf[2];
                bf[0] = __float_as_uint(Ksb[(nt * 8 + g) * 68 + ks * 8 + tg]);
                bf[1] = __float_as_uint(Ksb[(nt * 8 + g) * 68 + ks * 8 + tg + 4]);
                mma_tf32(s[nt], qf[ks], bf);
            }
        }

        // Causal mask (only tiles overlapping the diagonal: j >= 2*qt)
        if (j >= 2 * qt) {
            const int rg0 = qt * 128 + warp * 16 + g;
            const int rg1 = rg0 + 8;
            #pragma unroll
            for (int nt = 0; nt < 8; nt++) {
                const int c0 = j * 64 + nt * 8 + 2 * tg;
                if (c0     > rg0) s[nt][0] = -1e30f;
                if (c0 + 1 > rg0) s[nt][1] = -1e30f;
                if (c0     > rg1) s[nt][2] = -1e30f;
                if (c0 + 1 > rg1) s[nt][3] = -1e30f;
            }
        }

        // Online softmax (row g -> s[.][0,1], row g+8 -> s[.][2,3])
        float mt0 = -INFINITY, mt1 = -INFINITY;
        #pragma unroll
        for (int nt = 0; nt < 8; nt++) {
            mt0 = fmaxf(mt0, fmaxf(s[nt][0], s[nt][1]));
            mt1 = fmaxf(mt1, fmaxf(s[nt][2], s[nt][3]));
        }
        mt0 = fmaxf(mt0, __shfl_xor_sync(0xffffffffu, mt0, 1));
        mt0 = fmaxf(mt0, __shfl_xor_sync(0xffffffffu, mt0, 2));
        mt1 = fmaxf(mt1, __shfl_xor_sync(0xffffffffu, mt1, 1));
        mt1 = fmaxf(mt1, __shfl_xor_sync(0xffffffffu, mt1, 2));

        const float mn0 = fmaxf(m0, mt0), mn1 = fmaxf(m1, mt1);
        const float f0 = __expf(m0 - mn0), f1 = __expf(m1 - mn1);

        float ls0 = 0.f, ls1 = 0.f;
        float* prow0 = Pw + g * 68;
        float* prow1 = prow0 + 8 * 68;
        #pragma unroll
        for (int nt = 0; nt < 8; nt++) {
            const float p0 = __expf(s[nt][0] - mn0);
            const float p1 = __expf(s[nt][1] - mn0);
            const float p2 = __expf(s[nt][2] - mn1);
            const float p3 = __expf(s[nt][3] - mn1);
            ls0 += p0 + p1; ls1 += p2 + p3;
            const int c = nt * 8 + 2 * tg;
            *(float2*)&prow0[c] = make_float2(f2tf32(p0), f2tf32(p1));
            *(float2*)&prow1[c] = make_float2(f2tf32(p2), f2tf32(p3));
        }
        ls0 += __shfl_xor_sync(0xffffffffu, ls0, 1);
        ls0 += __shfl_xor_sync(0xffffffffu, ls0, 2);
        ls1 += __shfl_xor_sync(0xffffffffu, ls1, 1);
        ls1 += __shfl_xor_sync(0xffffffffu, ls1, 2);

        l0 = l0 * f0 + ls0;
        l1 = l1 * f1 + ls1;
        m0 = mn0; m1 = mn1;

        #pragma unroll
        for (int nt = 0; nt < 8; nt++) {
            o[nt][0] *= f0; o[nt][1] *= f0;
            o[nt][2] *= f1; o[nt][3] *= f1;
        }
        __syncwarp();   // per-warp P writes -> a-frag reads

        // O += P @ V   (V untransposed [kv][hd]; stride 68 is conflict-free)
        #pragma unroll
        for (int ks = 0; ks < 8; ks++) {
            uint32_t af[4];
            af[0] = __float_as_uint(Pw[g * 68 + ks * 8 + tg]);
            af[1] = __float_as_uint(Pw[(g + 8) * 68 + ks * 8 + tg]);
            af[2] = __float_as_uint(Pw[g * 68 + ks * 8 + tg + 4]);
            af[3] = __float_as_uint(Pw[(g + 8) * 68 + ks * 8 + tg + 4]);
            #pragma unroll
            for (int nt = 0; nt < 8; nt++) {
                uint32_t bf[2];
                bf[0] = __float_as_uint(Vsb[(ks * 8 + tg) * 68 + nt * 8 + g]);
                bf[1] = __float_as_uint(Vsb[(ks * 8 + tg + 4) * 68 + nt * 8 + g]);
                mma_tf32(o[nt], af, bf);
            }
        }
        __syncthreads();   // buf[cur] reads done before it is refilled at j+2
    }

    // Normalize, tf32-round (proj GEMM consumes y via cp.async), write
    const float i0 = 1.f / l0, i1 = 1.f / l1;
    const int r0 = b * T_ + qt * 128 + warp * 16 + g;
    #pragma unroll
    for (int nt = 0; nt < 8; nt++) {
        const int c = h * HD_ + nt * 8 + 2 * tg;
        *(float2*)&y[(size_t)r0 * C_ + c] =
            make_float2(f2tf32(o[nt][0] * i0), f2tf32(o[nt][1] * i0));
        *(float2*)&y[(size_t)(r0 + 8) * C_ + c] =
            make_float2(f2tf32(o[nt][2] * i1), f2tf32(o[nt][3] * i1));
    }
}

// ---------------------------------------------------------------------------
// Launch chain: round(x,wa,wp) -> qkv GEMM -> attention -> proj GEMM
// ---------------------------------------------------------------------------
extern "C" void kernel_launch(void* const* d_in, const int* in_sizes, int n_in,
                              void* d_out, int out_size)
{
    (void)in_sizes; (void)n_in; (void)out_size;
    const float* x      = (const float*)d_in[0];
    const float* w_attn = (const float*)d_in[1];
    const float* w_proj = (const float*)d_in[2];
    float* out = (float*)d_out;

    float *qkv, *y, *xr, *war, *wpr;
    cudaGetSymbolAddress((void**)&qkv, g_qkv);
    cudaGetSymbolAddress((void**)&y,   g_y);
    cudaGetSymbolAddress((void**)&xr,  g_xr);
    cudaGetSymbolAddress((void**)&war, g_war);
    cudaGetSymbolAddress((void**)&wpr, g_wpr);

    cudaFuncSetAttribute(gemm_tf32_cp<true>,  cudaFuncAttributeMaxDynamicSharedMemorySize, GEMM_SMEM);
    cudaFuncSetAttribute(gemm_tf32_cp<false>, cudaFuncAttributeMaxDynamicSharedMemorySize, GEMM_SMEM);
    cudaFuncSetAttribute(attn_kernel,         cudaFuncAttributeMaxDynamicSharedMemorySize, ATT_SMEM);

    const int n4x = ROWS_ * C_ / 4;       // 1048576
    const int n4a = C_ * C3_ / 4;         // 786432
    const int n4p = C_ * C_ / 4;          // 262144
    round_tf32_kernel<<<(n4x + 255) / 256, 256>>>((const float4*)x,      (float4*)xr,  n4x);
    round_tf32_kernel<<<(n4a + 255) / 256, 256>>>((const float4*)w_attn, (float4*)war, n4a);
    round_tf32_kernel<<<(n4p + 255) / 256, 256>>>((const float4*)w_proj, (float4*)wpr, n4p);

    gemm_tf32_cp<true><<<dim3(C3_ / GBN, ROWS_ / GBM), 256, GEMM_SMEM>>>(xr, war, qkv, ROWS_, C3_, C_);
    attn_kernel<<<dim3(T_ / 128, B_ * NH_), 256, ATT_SMEM>>>(qkv, y);
    gemm_tf32_cp<false><<<dim3(C_ / GBN, ROWS_ / GBM), 256, GEMM_SMEM>>>(y, wpr, out, ROWS_, C_, C_);
}